// round 8
// baseline (speedup 1.0000x reference)
#include <cuda_runtime.h>

#define TSTEPS  1024
#define BATCH   64
#define IN_DIM  256
#define HID_DIM 512
#define OUT_DIM 256
#define KDIM    768
#define NCTA    128
#define NTHR    512

// strides in floats
#define HSTRIDE_B (1025 * HID_DIM)
#define RSTRIDE_B (1025 * OUT_DIM)
#define XSTRIDE_B (TSTEPS * IN_DIM)

// ---- global-barrier state (init + final reset only) ----
__device__ unsigned g_bar_count = 0;
__device__ volatile unsigned g_bar_gen = 0;

// ---- per-half monotonic epoch counters (separate L2 sectors) ----
__device__ unsigned g_cnt[2 * 64];

__device__ __forceinline__ void grid_barrier() {
    __syncthreads();
    if (threadIdx.x == 0) {
        __threadfence();
        unsigned g = g_bar_gen;
        if (atomicAdd(&g_bar_count, 1u) == NCTA - 1) {
            g_bar_count = 0;
            __threadfence();
            g_bar_gen = g + 1;
        } else {
            while (g_bar_gen == g) {}
            __threadfence();
        }
    }
    __syncthreads();
}

__device__ __forceinline__ void red_release_add1(unsigned* p) {
    asm volatile("red.release.gpu.add.u32 [%0], 1;" :: "l"(p) : "memory");
}
__device__ __forceinline__ unsigned ld_acquire_u32(const unsigned* p) {
    unsigned v;
    asm volatile("ld.acquire.gpu.u32 %0, [%1];" : "=r"(v) : "l"(p) : "memory");
    return v;
}

// Persistent RNN kernel, v7 = v5 partition + pointer addressing + reg-hoisted
// loop-invariant weights (x-dot and r-dot) to cut L1tex/LDS traffic.
// 128 CTAs = 64 column-groups x 2 batch-halves. CTA = 512 threads = 16 warps.
//   warp = (col-half ch) x (batch-oct, 4 rows): 4 h-cols + 2 r-cols, 576 FFMA/thr.
__global__ void __launch_bounds__(NTHR, 1)
rnn_persistent_kernel(const float* __restrict__ X,    // [64][1024][256]
                      const float* __restrict__ H0,   // [64][512]
                      const float* __restrict__ R0,   // [64][256]
                      const float* __restrict__ Wih,  // [512][768]
                      const float* __restrict__ Bih,  // [512]
                      const float* __restrict__ Who,  // [256][768]
                      const float* __restrict__ Bho,  // [256]
                      float* __restrict__ Rout,       // [64][1025][256]
                      float* __restrict__ Hout)       // [64][1025][512]
{
    __shared__ float W1s[8][KDIM];   // W_ih rows jh0.. (k: 0..255 x | 256..767 h)
    __shared__ float W2s[4][KDIM];   // W_ho rows jr0.. (k: 0..511 h | 512..767 r)
    __shared__ float bih_s[8];
    __shared__ float bho_s[4];
    volatile __shared__ int bar_flag;

    const int tid  = threadIdx.x;
    const int cta  = blockIdx.x;
    const int grp  = cta >> 1;
    const int half = cta & 1;
    const int b0   = half * 32;
    const int jh0  = grp * 8;
    const int jr0  = grp * 4;
    const int wrp  = tid >> 5;
    const int lane = tid & 31;
    const int ch   = wrp >> 3;        // col half: 4 h-cols + 2 r-cols
    const int boct = wrp & 7;
    const int bb0  = b0 + boct * 4;
    unsigned* cnt  = &g_cnt[half * 64];

    // ---- stationary weight slices -> smem ----
    for (int idx = tid; idx < 8 * KDIM; idx += NTHR) {
        int j = idx / KDIM, k = idx - j * KDIM;
        W1s[j][k] = Wih[(jh0 + j) * KDIM + k];
    }
    for (int idx = tid; idx < 4 * KDIM; idx += NTHR) {
        int j = idx / KDIM, k = idx - j * KDIM;
        W2s[j][k] = Who[(jr0 + j) * KDIM + k];
    }
    if (tid < 8) bih_s[tid] = Bih[jh0 + tid];
    if (tid < 4) bho_s[tid] = Bho[jr0 + tid];
    if (tid == 0) bar_flag = 0;

    // ---- t=0 states into output/exchange buffers ----
    for (int idx = tid; idx < 32 * 8; idx += NTHR) {
        int b = b0 + (idx >> 3), jj = idx & 7;
        Hout[(size_t)b * HSTRIDE_B + jh0 + jj] = H0[b * HID_DIM + jh0 + jj];
    }
    for (int idx = tid; idx < 32 * 4; idx += NTHR) {
        int b = b0 + (idx >> 2), jj = idx & 3;
        Rout[(size_t)b * RSTRIDE_B + jr0 + jj] = R0[b * OUT_DIM + jr0 + jj];
    }
    __syncthreads();

    // ---- smem weight bases for the per-iter h-dot (stay in LDS) ----
    const float* W1p = &W1s[ch * 4][0];   // 4 h-col rows
    const float* W2p = &W2s[ch * 2][0];   // 2 r-col rows

    // ---- hoist loop-invariant weights into registers ----
    // x-dot: 2 k-steps x 4 cols = 8 float4 (32 regs)
    float4 wx[2][4];
#pragma unroll
    for (int i = 0; i < 2; ++i)
#pragma unroll
        for (int c = 0; c < 4; ++c)
            wx[i][c] = *(const float4*)&W1p[c * KDIM + 4 * lane + 128 * i];
    // r-dot: 2 k-steps x 2 cols = 4 float4 (16 regs)
    float4 wr[2][2];
#pragma unroll
    for (int i = 0; i < 2; ++i)
#pragma unroll
        for (int c = 0; c < 2; ++c)
            wr[i][c] = *(const float4*)&W2p[c * KDIM + 512 + 4 * lane + 128 * i];

    // ---- running pointers ----
    const float* pHr = Hout + (size_t)bb0 * HSTRIDE_B + 4 * lane;           // h[t=0]
    const float* pX  = X    + (size_t)bb0 * XSTRIDE_B + 4 * lane;           // x[t=0]
    const float* pRr = Rout + (size_t)bb0 * RSTRIDE_B + 4 * lane - OUT_DIM; // r[t=-1] (guarded)

    // per-lane store pointer + bias (lane < 24 stores; flat out idx = lane)
    const int bl = lane / 6, oc = lane % 6;
    float* pW = 0;
    float bias = 0.f;
    int   wstep = 0;
    if (lane < 24) {
        if (oc < 4) {   // h output, first store at t=1
            pW    = Hout + (size_t)(bb0 + bl) * HSTRIDE_B + HID_DIM + jh0 + ch * 4 + oc;
            bias  = bih_s[ch * 4 + oc];
            wstep = HID_DIM;
        } else {        // r output, first store at t=1 (it>=1 guard)
            pW    = Rout + (size_t)(bb0 + bl) * RSTRIDE_B + RSTRIDE_B / 1025 * 0 + OUT_DIM + jr0 + ch * 2 + (oc - 4);
            bias  = bho_s[ch * 2 + (oc - 4)];
            wstep = OUT_DIM;
        }
    }

    // A[b*6+c]: c 0..3 h-cols, c 4..5 r-cols
    float A[24];
#pragma unroll
    for (int i = 0; i < 24; ++i) A[i] = 0.f;

    // ---- prologue: x-dot for it=0 ----
#pragma unroll
    for (int i = 0; i < 2; ++i)
#pragma unroll
        for (int b = 0; b < 4; ++b) {
            const float4 a = *(const float4*)&pX[b * XSTRIDE_B + 128 * i];
#pragma unroll
            for (int c = 0; c < 4; ++c)
                A[b * 6 + c] += a.x * wx[i][c].x + a.y * wx[i][c].y
                              + a.z * wx[i][c].z + a.w * wx[i][c].w;
        }
    pX += IN_DIM;

    grid_barrier();  // one-time: H0/R0 copies visible grid-wide

    for (int it = 0; it <= TSTEPS; ++it) {
        // ---- h[it] feeds h-dot (W_ih k=256..767, LDS) and r-dot (W_ho k=0..511, LDS) ----
#pragma unroll
        for (int i = 0; i < 4; ++i) {
            float4 w1[4], w2[2];
#pragma unroll
            for (int c = 0; c < 4; ++c) w1[c] = *(const float4*)&W1p[c * KDIM + 256 + 4 * lane + 128 * i];
#pragma unroll
            for (int c = 0; c < 2; ++c) w2[c] = *(const float4*)&W2p[c * KDIM + 4 * lane + 128 * i];
#pragma unroll
            for (int b = 0; b < 4; ++b) {
                const float4 a = *(const float4*)&pHr[b * HSTRIDE_B + 128 * i];
#pragma unroll
                for (int c = 0; c < 4; ++c)
                    A[b * 6 + c] += a.x * w1[c].x + a.y * w1[c].y
                                  + a.z * w1[c].z + a.w * w1[c].w;
#pragma unroll
                for (int c = 0; c < 2; ++c)
                    A[b * 6 + 4 + c] += a.x * w2[c].x + a.y * w2[c].y
                                      + a.z * w2[c].z + a.w * w2[c].w;
            }
        }

        // ---- r[it-1] dot (register weights) ----
        if (it >= 1) {
#pragma unroll
            for (int i = 0; i < 2; ++i)
#pragma unroll
                for (int b = 0; b < 4; ++b) {
                    const float4 a = *(const float4*)&pRr[b * RSTRIDE_B + 128 * i];
#pragma unroll
                    for (int c = 0; c < 2; ++c)
                        A[b * 6 + 4 + c] += a.x * wr[i][c].x + a.y * wr[i][c].y
                                          + a.z * wr[i][c].z + a.w * wr[i][c].w;
                }
        }

        // ---- transpose-butterfly reduction: 31 shuffles, output L lands on lane L ----
#pragma unroll
        for (int off = 16; off >= 1; off >>= 1) {
#pragma unroll
            for (int i = 0; i < off && i < 24; ++i) {
                const int j = i + off;
                const float vj = (j < 24) ? A[j] : 0.f;
                const float send = (lane & off) ? A[i] : vj;
                const float recv = __shfl_xor_sync(0xffffffffu, send, off);
                const float keep = (lane & off) ? vj : A[i];
                A[i] = keep + recv;
            }
        }

        // ---- bias + relu + store ----
        if (lane < 24) {
            const float v = fmaxf(A[0] + bias, 0.f);
            if (oc < 4) {
                if (it < TSTEPS) *pW = v;      // h[it+1]
            } else {
                if (it >= 1) pW[-wstep] = v;   // r[it] (pointer pre-advanced to it+1 slot)
            }
        }

        if (it == TSTEPS) break;

        __syncthreads();                       // all CTA stores issued
        if (tid == 0) red_release_add1(cnt);   // arrive (release)

        // ---- wait window: zero accs, fold x-dot for it+1, advance pointers ----
#pragma unroll
        for (int i = 0; i < 24; ++i) A[i] = 0.f;
        if (it + 1 < TSTEPS) {
#pragma unroll
            for (int i = 0; i < 2; ++i)
#pragma unroll
                for (int b = 0; b < 4; ++b) {
                    const float4 a = *(const float4*)&pX[b * XSTRIDE_B + 128 * i];
#pragma unroll
                    for (int c = 0; c < 4; ++c)
                        A[b * 6 + c] += a.x * wx[i][c].x + a.y * wx[i][c].y
                                      + a.z * wx[i][c].z + a.w * wx[i][c].w;
                }
        }
        pX  += IN_DIM;
        pHr += HID_DIM;
        pRr += OUT_DIM;
        if (lane < 24) pW += wstep;

        // ---- wait for this half's epoch: t0 polls L2, relays via smem flag ----
        const int epoch = it + 1;
        if (tid == 0) {
            const unsigned tgt = 64u * (unsigned)epoch;
            while ((int)(ld_acquire_u32(cnt) - tgt) < 0) {}
            bar_flag = epoch;
        } else if (lane == 0) {
            while (bar_flag < epoch) {}
        }
        __syncwarp();
    }

    // ---- reset epoch counters for the next graph replay ----
    grid_barrier();
    if (cta < 2 && tid == 0) g_cnt[cta * 64] = 0;
}

extern "C" void kernel_launch(void* const* d_in, const int* in_sizes, int n_in,
                              void* d_out, int out_size) {
    const float* X   = (const float*)d_in[0];
    const float* H0  = (const float*)d_in[1];
    const float* R0  = (const float*)d_in[2];
    const float* Wih = (const float*)d_in[3];
    const float* Bih = (const float*)d_in[4];
    const float* Who = (const float*)d_in[5];
    const float* Bho = (const float*)d_in[6];

    float* Rout = (float*)d_out;                                   // [64][1025][256]
    float* Hout = (float*)d_out + (size_t)BATCH * 1025 * OUT_DIM;  // [64][1025][512]

    rnn_persistent_kernel<<<NCTA, NTHR>>>(X, H0, R0, Wih, Bih, Who, Bho, Rout, Hout);
}

// round 9
// speedup vs baseline: 1.0030x; 1.0030x over previous
#include <cuda_runtime.h>

#define TSTEPS  1024
#define BATCH   64
#define IN_DIM  256
#define HID_DIM 512
#define OUT_DIM 256
#define KDIM    768
#define NCTA    128
#define NTHR    512

// strides in floats
#define HSTRIDE_B (1025 * HID_DIM)
#define RSTRIDE_B (1025 * OUT_DIM)
#define XSTRIDE_B (TSTEPS * IN_DIM)

// ---- global-barrier state (init + final reset only) ----
__device__ unsigned g_bar_count = 0;
__device__ volatile unsigned g_bar_gen = 0;

// ---- per-half monotonic epoch counters (separate L2 sectors) ----
__device__ unsigned g_cnt[2 * 64];

__device__ __forceinline__ void grid_barrier() {
    __syncthreads();
    if (threadIdx.x == 0) {
        __threadfence();
        unsigned g = g_bar_gen;
        if (atomicAdd(&g_bar_count, 1u) == NCTA - 1) {
            g_bar_count = 0;
            __threadfence();
            g_bar_gen = g + 1;
        } else {
            while (g_bar_gen == g) {}
            __threadfence();
        }
    }
    __syncthreads();
}

__device__ __forceinline__ void red_release_add1(unsigned* p) {
    asm volatile("red.release.gpu.add.u32 [%0], 1;" :: "l"(p) : "memory");
}
__device__ __forceinline__ unsigned ld_acquire_u32(const unsigned* p) {
    unsigned v;
    asm volatile("ld.acquire.gpu.u32 %0, [%1];" : "=r"(v) : "l"(p) : "memory");
    return v;
}

// Persistent RNN kernel, v7 = v5 partition + pointer addressing + reg-hoisted
// loop-invariant weights (x-dot and r-dot) to cut L1tex/LDS traffic.
// 128 CTAs = 64 column-groups x 2 batch-halves. CTA = 512 threads = 16 warps.
//   warp = (col-half ch) x (batch-oct, 4 rows): 4 h-cols + 2 r-cols, 576 FFMA/thr.
__global__ void __launch_bounds__(NTHR, 1)
rnn_persistent_kernel(const float* __restrict__ X,    // [64][1024][256]
                      const float* __restrict__ H0,   // [64][512]
                      const float* __restrict__ R0,   // [64][256]
                      const float* __restrict__ Wih,  // [512][768]
                      const float* __restrict__ Bih,  // [512]
                      const float* __restrict__ Who,  // [256][768]
                      const float* __restrict__ Bho,  // [256]
                      float* __restrict__ Rout,       // [64][1025][256]
                      float* __restrict__ Hout)       // [64][1025][512]
{
    __shared__ float W1s[8][KDIM];   // W_ih rows jh0.. (k: 0..255 x | 256..767 h)
    __shared__ float W2s[4][KDIM];   // W_ho rows jr0.. (k: 0..511 h | 512..767 r)
    __shared__ float bih_s[8];
    __shared__ float bho_s[4];
    volatile __shared__ int bar_flag;

    const int tid  = threadIdx.x;
    const int cta  = blockIdx.x;
    const int grp  = cta >> 1;
    const int half = cta & 1;
    const int b0   = half * 32;
    const int jh0  = grp * 8;
    const int jr0  = grp * 4;
    const int wrp  = tid >> 5;
    const int lane = tid & 31;
    const int ch   = wrp >> 3;        // col half: 4 h-cols + 2 r-cols
    const int boct = wrp & 7;
    const int bb0  = b0 + boct * 4;
    unsigned* cnt  = &g_cnt[half * 64];

    // ---- stationary weight slices -> smem ----
    for (int idx = tid; idx < 8 * KDIM; idx += NTHR) {
        int j = idx / KDIM, k = idx - j * KDIM;
        W1s[j][k] = Wih[(jh0 + j) * KDIM + k];
    }
    for (int idx = tid; idx < 4 * KDIM; idx += NTHR) {
        int j = idx / KDIM, k = idx - j * KDIM;
        W2s[j][k] = Who[(jr0 + j) * KDIM + k];
    }
    if (tid < 8) bih_s[tid] = Bih[jh0 + tid];
    if (tid < 4) bho_s[tid] = Bho[jr0 + tid];
    if (tid == 0) bar_flag = 0;

    // ---- t=0 states into output/exchange buffers ----
    for (int idx = tid; idx < 32 * 8; idx += NTHR) {
        int b = b0 + (idx >> 3), jj = idx & 7;
        Hout[(size_t)b * HSTRIDE_B + jh0 + jj] = H0[b * HID_DIM + jh0 + jj];
    }
    for (int idx = tid; idx < 32 * 4; idx += NTHR) {
        int b = b0 + (idx >> 2), jj = idx & 3;
        Rout[(size_t)b * RSTRIDE_B + jr0 + jj] = R0[b * OUT_DIM + jr0 + jj];
    }
    __syncthreads();

    // ---- smem weight bases for the per-iter h-dot (stay in LDS) ----
    const float* W1p = &W1s[ch * 4][0];   // 4 h-col rows
    const float* W2p = &W2s[ch * 2][0];   // 2 r-col rows

    // ---- hoist loop-invariant weights into registers ----
    // x-dot: 2 k-steps x 4 cols = 8 float4 (32 regs)
    float4 wx[2][4];
#pragma unroll
    for (int i = 0; i < 2; ++i)
#pragma unroll
        for (int c = 0; c < 4; ++c)
            wx[i][c] = *(const float4*)&W1p[c * KDIM + 4 * lane + 128 * i];
    // r-dot: 2 k-steps x 2 cols = 4 float4 (16 regs)
    float4 wr[2][2];
#pragma unroll
    for (int i = 0; i < 2; ++i)
#pragma unroll
        for (int c = 0; c < 2; ++c)
            wr[i][c] = *(const float4*)&W2p[c * KDIM + 512 + 4 * lane + 128 * i];

    // ---- running pointers ----
    const float* pHr = Hout + (size_t)bb0 * HSTRIDE_B + 4 * lane;           // h[t=0]
    const float* pX  = X    + (size_t)bb0 * XSTRIDE_B + 4 * lane;           // x[t=0]
    const float* pRr = Rout + (size_t)bb0 * RSTRIDE_B + 4 * lane - OUT_DIM; // r[t=-1] (guarded)

    // per-lane store pointer + bias (lane < 24 stores; flat out idx = lane)
    const int bl = lane / 6, oc = lane % 6;
    float* pW = 0;
    float bias = 0.f;
    int   wstep = 0;
    if (lane < 24) {
        if (oc < 4) {   // h output, first store at t=1
            pW    = Hout + (size_t)(bb0 + bl) * HSTRIDE_B + HID_DIM + jh0 + ch * 4 + oc;
            bias  = bih_s[ch * 4 + oc];
            wstep = HID_DIM;
        } else {        // r output, first store at t=1 (it>=1 guard)
            pW    = Rout + (size_t)(bb0 + bl) * RSTRIDE_B + RSTRIDE_B / 1025 * 0 + OUT_DIM + jr0 + ch * 2 + (oc - 4);
            bias  = bho_s[ch * 2 + (oc - 4)];
            wstep = OUT_DIM;
        }
    }

    // A[b*6+c]: c 0..3 h-cols, c 4..5 r-cols
    float A[24];
#pragma unroll
    for (int i = 0; i < 24; ++i) A[i] = 0.f;

    // ---- prologue: x-dot for it=0 ----
#pragma unroll
    for (int i = 0; i < 2; ++i)
#pragma unroll
        for (int b = 0; b < 4; ++b) {
            const float4 a = *(const float4*)&pX[b * XSTRIDE_B + 128 * i];
#pragma unroll
            for (int c = 0; c < 4; ++c)
                A[b * 6 + c] += a.x * wx[i][c].x + a.y * wx[i][c].y
                              + a.z * wx[i][c].z + a.w * wx[i][c].w;
        }
    pX += IN_DIM;

    grid_barrier();  // one-time: H0/R0 copies visible grid-wide

    for (int it = 0; it <= TSTEPS; ++it) {
        // ---- h[it] feeds h-dot (W_ih k=256..767, LDS) and r-dot (W_ho k=0..511, LDS) ----
#pragma unroll
        for (int i = 0; i < 4; ++i) {
            float4 w1[4], w2[2];
#pragma unroll
            for (int c = 0; c < 4; ++c) w1[c] = *(const float4*)&W1p[c * KDIM + 256 + 4 * lane + 128 * i];
#pragma unroll
            for (int c = 0; c < 2; ++c) w2[c] = *(const float4*)&W2p[c * KDIM + 4 * lane + 128 * i];
#pragma unroll
            for (int b = 0; b < 4; ++b) {
                const float4 a = *(const float4*)&pHr[b * HSTRIDE_B + 128 * i];
#pragma unroll
                for (int c = 0; c < 4; ++c)
                    A[b * 6 + c] += a.x * w1[c].x + a.y * w1[c].y
                                  + a.z * w1[c].z + a.w * w1[c].w;
#pragma unroll
                for (int c = 0; c < 2; ++c)
                    A[b * 6 + 4 + c] += a.x * w2[c].x + a.y * w2[c].y
                                      + a.z * w2[c].z + a.w * w2[c].w;
            }
        }

        // ---- r[it-1] dot (register weights) ----
        if (it >= 1) {
#pragma unroll
            for (int i = 0; i < 2; ++i)
#pragma unroll
                for (int b = 0; b < 4; ++b) {
                    const float4 a = *(const float4*)&pRr[b * RSTRIDE_B + 128 * i];
#pragma unroll
                    for (int c = 0; c < 2; ++c)
                        A[b * 6 + 4 + c] += a.x * wr[i][c].x + a.y * wr[i][c].y
                                          + a.z * wr[i][c].z + a.w * wr[i][c].w;
                }
        }

        // ---- transpose-butterfly reduction: 31 shuffles, output L lands on lane L ----
#pragma unroll
        for (int off = 16; off >= 1; off >>= 1) {
#pragma unroll
            for (int i = 0; i < off && i < 24; ++i) {
                const int j = i + off;
                const float vj = (j < 24) ? A[j] : 0.f;
                const float send = (lane & off) ? A[i] : vj;
                const float recv = __shfl_xor_sync(0xffffffffu, send, off);
                const float keep = (lane & off) ? vj : A[i];
                A[i] = keep + recv;
            }
        }

        // ---- bias + relu + store ----
        if (lane < 24) {
            const float v = fmaxf(A[0] + bias, 0.f);
            if (oc < 4) {
                if (it < TSTEPS) *pW = v;      // h[it+1]
            } else {
                if (it >= 1) pW[-wstep] = v;   // r[it] (pointer pre-advanced to it+1 slot)
            }
        }

        if (it == TSTEPS) break;

        __syncthreads();                       // all CTA stores issued
        if (tid == 0) red_release_add1(cnt);   // arrive (release)

        // ---- wait window: zero accs, fold x-dot for it+1, advance pointers ----
#pragma unroll
        for (int i = 0; i < 24; ++i) A[i] = 0.f;
        if (it + 1 < TSTEPS) {
#pragma unroll
            for (int i = 0; i < 2; ++i)
#pragma unroll
                for (int b = 0; b < 4; ++b) {
                    const float4 a = *(const float4*)&pX[b * XSTRIDE_B + 128 * i];
#pragma unroll
                    for (int c = 0; c < 4; ++c)
                        A[b * 6 + c] += a.x * wx[i][c].x + a.y * wx[i][c].y
                                      + a.z * wx[i][c].z + a.w * wx[i][c].w;
                }
        }
        pX  += IN_DIM;
        pHr += HID_DIM;
        pRr += OUT_DIM;
        if (lane < 24) pW += wstep;

        // ---- wait for this half's epoch: t0 polls L2, relays via smem flag ----
        const int epoch = it + 1;
        if (tid == 0) {
            const unsigned tgt = 64u * (unsigned)epoch;
            while ((int)(ld_acquire_u32(cnt) - tgt) < 0) {}
            bar_flag = epoch;
        } else if (lane == 0) {
            while (bar_flag < epoch) {}
        }
        __syncwarp();
    }

    // ---- reset epoch counters for the next graph replay ----
    grid_barrier();
    if (cta < 2 && tid == 0) g_cnt[cta * 64] = 0;
}

extern "C" void kernel_launch(void* const* d_in, const int* in_sizes, int n_in,
                              void* d_out, int out_size) {
    const float* X   = (const float*)d_in[0];
    const float* H0  = (const float*)d_in[1];
    const float* R0  = (const float*)d_in[2];
    const float* Wih = (const float*)d_in[3];
    const float* Bih = (const float*)d_in[4];
    const float* Who = (const float*)d_in[5];
    const float* Bho = (const float*)d_in[6];

    float* Rout = (float*)d_out;                                   // [64][1025][256]
    float* Hout = (float*)d_out + (size_t)BATCH * 1025 * OUT_DIM;  // [64][1025][512]

    rnn_persistent_kernel<<<NCTA, NTHR>>>(X, H0, R0, Wih, Bih, Who, Bho, Rout, Hout);
}